// round 12
// baseline (speedup 1.0000x reference)
#include <cuda_runtime.h>

// x [B=8, C=64, T=32, H=56, W=56], window 7, eps 1e-5.
#define BB    8
#define CC    64
#define TT    32
#define HWV   (56 * 56)              // 3136 floats per plane
#define HW4   (HWV / 4)              // 784 float4 per (b,c,t) plane
#define NBC   (BB * CC)              // 512 (b,c) slabs
#define NCOL  (NBC * HW4)            // 401408 float4-columns total
#define BS    256                    // threads per block
#define NBLK  (NCOL / BS)            // 1568 blocks, exact
#define SLAB  (TT * HW4)             // 25088 float4 per (b,c) slab
#define NPC   ((double)(BB * TT * HWV))  // 802816 elements per channel

// Per-block two-segment fp32 partials (sums of u = rp/2):
// [blk] = {sum_lo, sumsq_lo, sum_hi, sumsq_hi}
__device__ float g_part[NBLK * 4];

// u = rp/2 = 3*(x_t - x_{t-6}) + 2*(x_{t-1} - x_{t-5}) + (x_{t-2} - x_{t-4})
// window regs: w0..w5 = x_{t-6}..x_{t-1}
#define U_COMP(comp, xv)                                                      \
    fmaf(3.0f, (xv).comp - w0.comp,                                           \
         fmaf(2.0f, w5.comp - w1.comp, w4.comp - w2.comp))

// ---------------- Pass 1: per-column rp stats, fp32 two-segment reduce -----
__global__ __launch_bounds__(BS) void datt_pass1(const float4* __restrict__ x4) {
    const int cid = blockIdx.x * BS + threadIdx.x;   // < NCOL exactly
    const int bc  = cid / HW4;
    const int p   = cid - bc * HW4;
    const float4* __restrict__ q = x4 + (size_t)bc * SLAB + p;

    float s = 0.0f, ss = 0.0f;
    float4 w0 = {0.f, 0.f, 0.f, 0.f};
    float4 w1 = w0, w2 = w0, w3 = w0, w4 = w0, w5 = w0;
#pragma unroll
    for (int t = 0; t < TT; t++) {
        float4 xv = q[t * HW4];
        float ux = U_COMP(x, xv);
        float uy = U_COMP(y, xv);
        float uz = U_COMP(z, xv);
        float uw = U_COMP(w, xv);
        s += (ux + uy) + (uz + uw);
        ss = fmaf(ux, ux, ss);
        ss = fmaf(uy, uy, ss);
        ss = fmaf(uz, uz, ss);
        ss = fmaf(uw, uw, ss);
        w0 = w1; w1 = w2; w2 = w3; w3 = w4; w4 = w5; w5 = xv;
    }

    // Two-segment fp32 reduction: a 256-thread block spans at most one bc
    // boundary (256 < 784). Segment 0 = bc_lo, segment 1 = bc_lo + 1.
    const int bc_lo = (blockIdx.x * BS) / HW4;
    const bool hi = (bc != bc_lo);
    float s0 = hi ? 0.0f : s;
    float q0 = hi ? 0.0f : ss;
    float s1 = hi ? s : 0.0f;
    float q1 = hi ? ss : 0.0f;
#pragma unroll
    for (int o = 16; o > 0; o >>= 1) {
        s0 += __shfl_down_sync(0xFFFFFFFFu, s0, o);
        q0 += __shfl_down_sync(0xFFFFFFFFu, q0, o);
        s1 += __shfl_down_sync(0xFFFFFFFFu, s1, o);
        q1 += __shfl_down_sync(0xFFFFFFFFu, q1, o);
    }
    __shared__ float sh[8][4];
    const int lane = threadIdx.x & 31, wid = threadIdx.x >> 5;
    if (lane == 0) { sh[wid][0] = s0; sh[wid][1] = q0; sh[wid][2] = s1; sh[wid][3] = q1; }
    __syncthreads();
    if (threadIdx.x == 0) {
        float a0 = 0.f, b0 = 0.f, a1 = 0.f, b1 = 0.f;
#pragma unroll
        for (int i = 0; i < 8; i++) {
            a0 += sh[i][0]; b0 += sh[i][1]; a1 += sh[i][2]; b1 += sh[i][3];
        }
        float4 pv = {a0, b0, a1, b1};
        *reinterpret_cast<float4*>(g_part + (size_t)blockIdx.x * 4) = pv;
    }
}

// ---------------- Pass 2: inline finalize + rp recompute + BN/ReLU/gate ----
// Warps 0/1 gather the <=32 segment partials for this block's 1-2 channels
// (each slab spans at most 4 pass1 blocks: (16*bc mod 256) <= 240, so
// r+783 <= 1023), reduce in double (fixed lane map + fixed shfl tree =>
// deterministic), broadcast scale/bias via smem.
// Then: out = x * (k1 + k2*relu(sc2*u + bi)).
// Reverse block order so first-scheduled blocks read the x slabs pass1 left
// in L2; __stwt keeps the out stream entirely out of L2.
__global__ __launch_bounds__(BS) void datt_pass2(const float4* __restrict__ x4,
                                                 float4* __restrict__ o4,
                                                 const float* __restrict__ gamma,
                                                 const float* __restrict__ beta,
                                                 const float* __restrict__ rpw) {
    const int cid_base = (NBLK - 1 - blockIdx.x) * BS;
    const int bc_lo = cid_base / HW4;
    const int bc_hi = (cid_base + BS - 1) / HW4;   // == bc_lo or bc_lo + 1

    __shared__ float sh_sc[2], sh_bi[2], sh_k[2];

    const int wid = threadIdx.x >> 5, lane = threadIdx.x & 31;
    if (wid < 2) {
        const int bc_t = wid ? bc_hi : bc_lo;      // wid1 redundant if equal; harmless
        const int c = bc_t & (CC - 1);
        const int bbv = lane >> 2, j = lane & 3;   // 8 slabs x up-to-4 blocks
        const int sbc = bbv * CC + c;
        const int k0  = (sbc * HW4) / BS;
        const int kk1 = (sbc * HW4 + HW4 - 1) / BS;
        const int k   = k0 + j;
        double S = 0.0, SS = 0.0;
        if (k <= kk1) {
            const int lo = (k * BS) / HW4;
            const int hh = (k * BS + BS - 1) / HW4;
            float4 g = *reinterpret_cast<const float4*>(g_part + (size_t)k * 4);
            if (lo == sbc) { S += (double)g.x; SS += (double)g.y; }
            if (hh == sbc) { S += (double)g.z; SS += (double)g.w; }  // seg1==0 if interior
        }
#pragma unroll
        for (int o = 16; o > 0; o >>= 1) {
            S  += __shfl_down_sync(0xFFFFFFFFu, S, o);
            SS += __shfl_down_sync(0xFFFFFFFFu, SS, o);
        }
        if (lane == 0) {
            // sums were of u = rp/2:  sum_rp = 2S,  sumsq_rp = 4SS
            const double mean = 2.0 * S / NPC;
            const double var  = 4.0 * SS / NPC - mean * mean;
            const double sc   = (double)gamma[c] / sqrt(var + 1e-5);
            sh_sc[wid] = (float)(2.0 * sc);                    // applied to u
            sh_bi[wid] = (float)((double)beta[c] - mean * sc);
            if (wid == 0) {
                const float r0 = rpw[0], r1 = rpw[1];
                sh_k[0] = r0 + r1;   // k1
                sh_k[1] = r1;        // k2
            }
        }
    }
    __syncthreads();

    const int cid = cid_base + threadIdx.x;
    const int bc  = cid / HW4;
    const int sel = (bc != bc_lo) ? 1 : 0;
    const float sc2 = sh_sc[sel];
    const float bi  = sh_bi[sel];
    const float k1  = sh_k[0];
    const float k2  = sh_k[1];

    const size_t off = (size_t)bc * SLAB + (cid - bc * HW4);
    const float4* __restrict__ q = x4 + off;
    float4* __restrict__ o = o4 + off;

    float4 w0 = {0.f, 0.f, 0.f, 0.f};
    float4 w1 = w0, w2 = w0, w3 = w0, w4 = w0, w5 = w0;
#pragma unroll
    for (int t = 0; t < TT; t++) {
        float4 xv = __ldcs(q + t * HW4);   // streaming: last use of this line
        float yx = fmaxf(fmaf(U_COMP(x, xv), sc2, bi), 0.0f);
        float yy = fmaxf(fmaf(U_COMP(y, xv), sc2, bi), 0.0f);
        float yz = fmaxf(fmaf(U_COMP(z, xv), sc2, bi), 0.0f);
        float yw = fmaxf(fmaf(U_COMP(w, xv), sc2, bi), 0.0f);
        float4 ov;
        ov.x = xv.x * fmaf(k2, yx, k1);
        ov.y = xv.y * fmaf(k2, yy, k1);
        ov.z = xv.z * fmaf(k2, yz, k1);
        ov.w = xv.w * fmaf(k2, yw, k1);
        __stwt(o + t * HW4, ov);           // write-through: zero L2 footprint
        w0 = w1; w1 = w2; w2 = w3; w3 = w4; w4 = w5; w5 = xv;
    }
}

extern "C" void kernel_launch(void* const* d_in, const int* in_sizes, int n_in,
                              void* d_out, int out_size) {
    const float4* x4   = (const float4*)d_in[0];  // [8,64,32,56,56]
    const float* gamma = (const float*)d_in[1];   // [64]
    const float* beta  = (const float*)d_in[2];   // [64]
    const float* rpw   = (const float*)d_in[3];   // [2]
    float4* out4 = (float4*)d_out;

    datt_pass1<<<NBLK, BS>>>(x4);
    datt_pass2<<<NBLK, BS>>>(x4, out4, gamma, beta, rpw);
}

// round 13
// speedup vs baseline: 1.0328x; 1.0328x over previous
#include <cuda_runtime.h>

// x [B=8, C=64, T=32, H=56, W=56], window 7, eps 1e-5.
#define BB    8
#define CC    64
#define TT    32
#define HWV   (56 * 56)              // 3136 floats per plane
#define HW4   (HWV / 4)              // 784 float4 per (b,c,t) plane
#define NBC   (BB * CC)              // 512 (b,c) slabs
#define NCOL  (NBC * HW4)            // 401408 float4-columns total
#define BS    256                    // threads per block
#define NBLK  (NCOL / BS)            // 1568 blocks, exact
#define SLAB  (TT * HW4)             // 25088 float4 per (b,c) slab
#define NPC   ((double)(BB * TT * HWV))  // 802816 elements per channel

// Per-block two-segment fp32 partials (sums of u = rp/2):
// [blk] = {sum_lo, sumsq_lo, sum_hi, sumsq_hi}
__device__ float g_part[NBLK * 4];

// u = rp/2 = 3*(x_t - x_{t-6}) + 2*(x_{t-1} - x_{t-5}) + (x_{t-2} - x_{t-4})
// window regs: w0..w5 = x_{t-6}..x_{t-1}
#define U_COMP(comp, xv)                                                      \
    fmaf(3.0f, (xv).comp - w0.comp,                                           \
         fmaf(2.0f, w5.comp - w1.comp, w4.comp - w2.comp))

// ---------------- Pass 1: per-column rp stats, fp32 two-segment reduce -----
__global__ __launch_bounds__(BS) void datt_pass1(const float4* __restrict__ x4) {
    const int cid = blockIdx.x * BS + threadIdx.x;   // < NCOL exactly
    const int bc  = cid / HW4;
    const int p   = cid - bc * HW4;
    const float4* __restrict__ q = x4 + (size_t)bc * SLAB + p;

    float s = 0.0f, ss = 0.0f;
    float4 w0 = {0.f, 0.f, 0.f, 0.f};
    float4 w1 = w0, w2 = w0, w3 = w0, w4 = w0, w5 = w0;
#pragma unroll
    for (int t = 0; t < TT; t++) {
        float4 xv = q[t * HW4];
        float ux = U_COMP(x, xv);
        float uy = U_COMP(y, xv);
        float uz = U_COMP(z, xv);
        float uw = U_COMP(w, xv);
        s += (ux + uy) + (uz + uw);
        ss = fmaf(ux, ux, ss);
        ss = fmaf(uy, uy, ss);
        ss = fmaf(uz, uz, ss);
        ss = fmaf(uw, uw, ss);
        w0 = w1; w1 = w2; w2 = w3; w3 = w4; w4 = w5; w5 = xv;
    }

    // Two-segment fp32 reduction: a 256-thread block spans at most one bc
    // boundary (256 < 784). Segment 0 = bc_lo, segment 1 = bc_lo + 1.
    const int bc_lo = (blockIdx.x * BS) / HW4;
    const bool hi = (bc != bc_lo);
    float s0 = hi ? 0.0f : s;
    float q0 = hi ? 0.0f : ss;
    float s1 = hi ? s : 0.0f;
    float q1 = hi ? ss : 0.0f;
#pragma unroll
    for (int o = 16; o > 0; o >>= 1) {
        s0 += __shfl_down_sync(0xFFFFFFFFu, s0, o);
        q0 += __shfl_down_sync(0xFFFFFFFFu, q0, o);
        s1 += __shfl_down_sync(0xFFFFFFFFu, s1, o);
        q1 += __shfl_down_sync(0xFFFFFFFFu, q1, o);
    }
    __shared__ float sh[8][4];
    const int lane = threadIdx.x & 31, wid = threadIdx.x >> 5;
    if (lane == 0) { sh[wid][0] = s0; sh[wid][1] = q0; sh[wid][2] = s1; sh[wid][3] = q1; }
    __syncthreads();
    if (threadIdx.x == 0) {
        float a0 = 0.f, b0 = 0.f, a1 = 0.f, b1 = 0.f;
#pragma unroll
        for (int i = 0; i < 8; i++) {
            a0 += sh[i][0]; b0 += sh[i][1]; a1 += sh[i][2]; b1 += sh[i][3];
        }
        float4 pv = {a0, b0, a1, b1};
        *reinterpret_cast<float4*>(g_part + (size_t)blockIdx.x * 4) = pv;
    }
}

// ---------------- Pass 2: inline finalize + rp recompute + BN/ReLU/gate ----
// Warps 0/1 gather the <=32 segment partials for this block's 1-2 channels
// (each slab spans at most 4 pass1 blocks), reduce in double (fixed lane map
// + fixed shfl tree => deterministic), broadcast scale/bias via smem.
// Then: out = x * (k1 + k2*relu(sc2*u + bi)), __ldcs/__stcs streaming.
__global__ __launch_bounds__(BS) void datt_pass2(const float4* __restrict__ x4,
                                                 float4* __restrict__ o4,
                                                 const float* __restrict__ gamma,
                                                 const float* __restrict__ beta,
                                                 const float* __restrict__ rpw) {
    const int cid_base = (NBLK - 1 - blockIdx.x) * BS;
    const int bc_lo = cid_base / HW4;
    const int bc_hi = (cid_base + BS - 1) / HW4;   // == bc_lo or bc_lo + 1

    __shared__ float sh_sc[2], sh_bi[2], sh_k[2];

    const int wid = threadIdx.x >> 5, lane = threadIdx.x & 31;
    if (wid < 2) {
        const int bc_t = wid ? bc_hi : bc_lo;      // wid1 redundant if equal; harmless
        const int c = bc_t & (CC - 1);
        const int bbv = lane >> 2, j = lane & 3;   // 8 slabs x up-to-4 blocks
        const int sbc = bbv * CC + c;
        const int k0  = (sbc * HW4) / BS;
        const int kk1 = (sbc * HW4 + HW4 - 1) / BS;
        const int k   = k0 + j;
        double S = 0.0, SS = 0.0;
        if (k <= kk1) {
            const int lo = (k * BS) / HW4;
            const int hh = (k * BS + BS - 1) / HW4;
            float4 g = *reinterpret_cast<const float4*>(g_part + (size_t)k * 4);
            if (lo == sbc) { S += (double)g.x; SS += (double)g.y; }
            if (hh == sbc) { S += (double)g.z; SS += (double)g.w; }  // seg1==0 if interior
        }
#pragma unroll
        for (int o = 16; o > 0; o >>= 1) {
            S  += __shfl_down_sync(0xFFFFFFFFu, S, o);
            SS += __shfl_down_sync(0xFFFFFFFFu, SS, o);
        }
        if (lane == 0) {
            // sums were of u = rp/2:  sum_rp = 2S,  sumsq_rp = 4SS
            const double mean = 2.0 * S / NPC;
            const double var  = 4.0 * SS / NPC - mean * mean;
            const double sc   = (double)gamma[c] / sqrt(var + 1e-5);
            sh_sc[wid] = (float)(2.0 * sc);                    // applied to u
            sh_bi[wid] = (float)((double)beta[c] - mean * sc);
            if (wid == 0) {
                const float r0 = rpw[0], r1 = rpw[1];
                sh_k[0] = r0 + r1;   // k1
                sh_k[1] = r1;        // k2
            }
        }
    }
    __syncthreads();

    const int cid = cid_base + threadIdx.x;
    const int bc  = cid / HW4;
    const int sel = (bc != bc_lo) ? 1 : 0;
    const float sc2 = sh_sc[sel];
    const float bi  = sh_bi[sel];
    const float k1  = sh_k[0];
    const float k2  = sh_k[1];

    const size_t off = (size_t)bc * SLAB + (cid - bc * HW4);
    const float4* __restrict__ q = x4 + off;
    float4* __restrict__ o = o4 + off;

    float4 w0 = {0.f, 0.f, 0.f, 0.f};
    float4 w1 = w0, w2 = w0, w3 = w0, w4 = w0, w5 = w0;
#pragma unroll
    for (int t = 0; t < TT; t++) {
        float4 xv = __ldcs(q + t * HW4);   // streaming: last use of this line
        float yx = fmaxf(fmaf(U_COMP(x, xv), sc2, bi), 0.0f);
        float yy = fmaxf(fmaf(U_COMP(y, xv), sc2, bi), 0.0f);
        float yz = fmaxf(fmaf(U_COMP(z, xv), sc2, bi), 0.0f);
        float yw = fmaxf(fmaf(U_COMP(w, xv), sc2, bi), 0.0f);
        float4 ov;
        ov.x = xv.x * fmaf(k2, yx, k1);
        ov.y = xv.y * fmaf(k2, yy, k1);
        ov.z = xv.z * fmaf(k2, yz, k1);
        ov.w = xv.w * fmaf(k2, yw, k1);
        __stcs(o + t * HW4, ov);           // streaming store (confirmed best)
        w0 = w1; w1 = w2; w2 = w3; w3 = w4; w4 = w5; w5 = xv;
    }
}

extern "C" void kernel_launch(void* const* d_in, const int* in_sizes, int n_in,
                              void* d_out, int out_size) {
    const float4* x4   = (const float4*)d_in[0];  // [8,64,32,56,56]
    const float* gamma = (const float*)d_in[1];   // [64]
    const float* beta  = (const float*)d_in[2];   // [64]
    const float* rpw   = (const float*)d_in[3];   // [2]
    float4* out4 = (float4*)d_out;

    datt_pass1<<<NBLK, BS>>>(x4);
    datt_pass2<<<NBLK, BS>>>(x4, out4, gamma, beta, rpw);
}

// round 16
// speedup vs baseline: 1.1751x; 1.1378x over previous
#include <cuda_runtime.h>

// x [B=8, C=64, T=32, H=56, W=56], window 7, eps 1e-5.
#define BB    8
#define CC    64
#define TT    32
#define HWV   (56 * 56)              // 3136 floats per plane
#define HW4   (HWV / 4)              // 784 float4 per (b,c,t) plane
#define NBC   (BB * CC)              // 512 (b,c) slabs
#define NCOL  (NBC * HW4)            // 401408 float4-columns total
#define BS    256                    // threads per block
#define NBLK  (NCOL / BS)            // 1568 blocks, exact
#define SLAB  (TT * HW4)             // 25088 float4 per (b,c) slab
#define NPC   ((double)(BB * TT * HWV))  // 802816 elements per channel

// Per-block two-segment fp32 partials (sums of u = rp/2):
// [blk] = {sum_lo, sumsq_lo, sum_hi, sumsq_hi}
__device__ float g_part[NBLK * 4];

// u = rp/2 = 3*(x_t - x_{t-6}) + 2*(x_{t-1} - x_{t-5}) + (x_{t-2} - x_{t-4})
// window regs: w0..w5 = x_{t-6}..x_{t-1}
#define U_COMP(comp, xv)                                                      \
    fmaf(3.0f, (xv).comp - w0.comp,                                           \
         fmaf(2.0f, w5.comp - w1.comp, w4.comp - w2.comp))

#define RING_SHIFT(xv)                                                        \
    do { w0 = w1; w1 = w2; w2 = w3; w3 = w4; w4 = w5; w5 = (xv); } while (0)

// ---------------- Pass 1: per-column rp stats, chunk-4 prefetch ------------
__global__ __launch_bounds__(BS) void datt_pass1(const float4* __restrict__ x4) {
    const int cid = blockIdx.x * BS + threadIdx.x;   // < NCOL exactly
    const int bc  = cid / HW4;
    const int p   = cid - bc * HW4;
    const float4* __restrict__ q = x4 + (size_t)bc * SLAB + p;

    float s = 0.0f, ss = 0.0f;
    float4 w0 = {0.f, 0.f, 0.f, 0.f};
    float4 w1 = w0, w2 = w0, w3 = w0, w4 = w0, w5 = w0;

#pragma unroll
    for (int tc = 0; tc < TT; tc += 4) {
        // 4 back-to-back loads: MLP 4, 2KB read burst per warp
        float4 a0 = q[(tc + 0) * HW4];
        float4 a1 = q[(tc + 1) * HW4];
        float4 a2 = q[(tc + 2) * HW4];
        float4 a3 = q[(tc + 3) * HW4];
#pragma unroll
        for (int j = 0; j < 4; j++) {
            float4 xv = (j == 0) ? a0 : (j == 1) ? a1 : (j == 2) ? a2 : a3;
            float ux = U_COMP(x, xv);
            float uy = U_COMP(y, xv);
            float uz = U_COMP(z, xv);
            float uw = U_COMP(w, xv);
            s += (ux + uy) + (uz + uw);
            ss = fmaf(ux, ux, ss);
            ss = fmaf(uy, uy, ss);
            ss = fmaf(uz, uz, ss);
            ss = fmaf(uw, uw, ss);
            RING_SHIFT(xv);
        }
    }

    // Two-segment fp32 reduction: a 256-thread block spans at most one bc
    // boundary (256 < 784). Segment 0 = bc_lo, segment 1 = bc_lo + 1.
    const int bc_lo = (blockIdx.x * BS) / HW4;
    const bool hi = (bc != bc_lo);
    float s0 = hi ? 0.0f : s;
    float q0 = hi ? 0.0f : ss;
    float s1 = hi ? s : 0.0f;
    float q1 = hi ? ss : 0.0f;
#pragma unroll
    for (int o = 16; o > 0; o >>= 1) {
        s0 += __shfl_down_sync(0xFFFFFFFFu, s0, o);
        q0 += __shfl_down_sync(0xFFFFFFFFu, q0, o);
        s1 += __shfl_down_sync(0xFFFFFFFFu, s1, o);
        q1 += __shfl_down_sync(0xFFFFFFFFu, q1, o);
    }
    __shared__ float sh[8][4];
    const int lane = threadIdx.x & 31, wid = threadIdx.x >> 5;
    if (lane == 0) { sh[wid][0] = s0; sh[wid][1] = q0; sh[wid][2] = s1; sh[wid][3] = q1; }
    __syncthreads();
    if (threadIdx.x == 0) {
        float a0 = 0.f, b0 = 0.f, a1 = 0.f, b1 = 0.f;
#pragma unroll
        for (int i = 0; i < 8; i++) {
            a0 += sh[i][0]; b0 += sh[i][1]; a1 += sh[i][2]; b1 += sh[i][3];
        }
        float4 pv = {a0, b0, a1, b1};
        *reinterpret_cast<float4*>(g_part + (size_t)blockIdx.x * 4) = pv;
    }
}

// ---------------- Pass 2: inline finalize + chunk-4 rp/BN/ReLU/gate --------
// Warps 0/1 gather the <=32 segment partials for this block's 1-2 channels,
// reduce in double (fixed lane map + shfl tree => deterministic), broadcast
// via smem. Main loop: 4 loads -> 4 computes -> 4 stores per chunk.
__global__ __launch_bounds__(BS) void datt_pass2(const float4* __restrict__ x4,
                                                 float4* __restrict__ o4,
                                                 const float* __restrict__ gamma,
                                                 const float* __restrict__ beta,
                                                 const float* __restrict__ rpw) {
    const int cid_base = (NBLK - 1 - blockIdx.x) * BS;
    const int bc_lo = cid_base / HW4;
    const int bc_hi = (cid_base + BS - 1) / HW4;   // == bc_lo or bc_lo + 1

    __shared__ float sh_sc[2], sh_bi[2], sh_k[2];

    const int wid = threadIdx.x >> 5, lane = threadIdx.x & 31;
    if (wid < 2) {
        const int bc_t = wid ? bc_hi : bc_lo;      // wid1 redundant if equal; harmless
        const int c = bc_t & (CC - 1);
        const int bbv = lane >> 2, j = lane & 3;   // 8 slabs x up-to-4 blocks
        const int sbc = bbv * CC + c;
        const int k0  = (sbc * HW4) / BS;
        const int kk1 = (sbc * HW4 + HW4 - 1) / BS;
        const int k   = k0 + j;
        double S = 0.0, SS = 0.0;
        if (k <= kk1) {
            const int lo = (k * BS) / HW4;
            const int hh = (k * BS + BS - 1) / HW4;
            float4 g = *reinterpret_cast<const float4*>(g_part + (size_t)k * 4);
            if (lo == sbc) { S += (double)g.x; SS += (double)g.y; }
            if (hh == sbc) { S += (double)g.z; SS += (double)g.w; }  // seg1==0 if interior
        }
#pragma unroll
        for (int o = 16; o > 0; o >>= 1) {
            S  += __shfl_down_sync(0xFFFFFFFFu, S, o);
            SS += __shfl_down_sync(0xFFFFFFFFu, SS, o);
        }
        if (lane == 0) {
            // sums were of u = rp/2:  sum_rp = 2S,  sumsq_rp = 4SS
            const double mean = 2.0 * S / NPC;
            const double var  = 4.0 * SS / NPC - mean * mean;
            const double sc   = (double)gamma[c] / sqrt(var + 1e-5);
            sh_sc[wid] = (float)(2.0 * sc);                    // applied to u
            sh_bi[wid] = (float)((double)beta[c] - mean * sc);
            if (wid == 0) {
                const float r0 = rpw[0], r1 = rpw[1];
                sh_k[0] = r0 + r1;   // k1
                sh_k[1] = r1;        // k2
            }
        }
    }
    __syncthreads();

    const int cid = cid_base + threadIdx.x;
    const int bc  = cid / HW4;
    const int sel = (bc != bc_lo) ? 1 : 0;
    const float sc2 = sh_sc[sel];
    const float bi  = sh_bi[sel];
    const float k1  = sh_k[0];
    const float k2  = sh_k[1];

    const size_t off = (size_t)bc * SLAB + (cid - bc * HW4);
    const float4* __restrict__ q = x4 + off;
    float4* __restrict__ o = o4 + off;

    float4 w0 = {0.f, 0.f, 0.f, 0.f};
    float4 w1 = w0, w2 = w0, w3 = w0, w4 = w0, w5 = w0;

#pragma unroll
    for (int tc = 0; tc < TT; tc += 4) {
        // 4 back-to-back streaming loads (MLP 4, 2KB read burst)
        float4 a0 = __ldcs(q + (tc + 0) * HW4);
        float4 a1 = __ldcs(q + (tc + 1) * HW4);
        float4 a2 = __ldcs(q + (tc + 2) * HW4);
        float4 a3 = __ldcs(q + (tc + 3) * HW4);
        float4 ov0, ov1, ov2, ov3;
#pragma unroll
        for (int j = 0; j < 4; j++) {
            float4 xv = (j == 0) ? a0 : (j == 1) ? a1 : (j == 2) ? a2 : a3;
            float yx = fmaxf(fmaf(U_COMP(x, xv), sc2, bi), 0.0f);
            float yy = fmaxf(fmaf(U_COMP(y, xv), sc2, bi), 0.0f);
            float yz = fmaxf(fmaf(U_COMP(z, xv), sc2, bi), 0.0f);
            float yw = fmaxf(fmaf(U_COMP(w, xv), sc2, bi), 0.0f);
            float4 ov;
            ov.x = xv.x * fmaf(k2, yx, k1);
            ov.y = xv.y * fmaf(k2, yy, k1);
            ov.z = xv.z * fmaf(k2, yz, k1);
            ov.w = xv.w * fmaf(k2, yw, k1);
            if (j == 0) ov0 = ov; else if (j == 1) ov1 = ov;
            else if (j == 2) ov2 = ov; else ov3 = ov;
            RING_SHIFT(xv);
        }
        // 4 back-to-back streaming stores (2KB write burst)
        __stcs(o + (tc + 0) * HW4, ov0);
        __stcs(o + (tc + 1) * HW4, ov1);
        __stcs(o + (tc + 2) * HW4, ov2);
        __stcs(o + (tc + 3) * HW4, ov3);
    }
}

extern "C" void kernel_launch(void* const* d_in, const int* in_sizes, int n_in,
                              void* d_out, int out_size) {
    const float4* x4   = (const float4*)d_in[0];  // [8,64,32,56,56]
    const float* gamma = (const float*)d_in[1];   // [64]
    const float* beta  = (const float*)d_in[2];   // [64]
    const float* rpw   = (const float*)d_in[3];   // [2]
    float4* out4 = (float4*)d_out;

    datt_pass1<<<NBLK, BS>>>(x4);
    datt_pass2<<<NBLK, BS>>>(x4, out4, gamma, beta, rpw);
}